// round 11
// baseline (speedup 1.0000x reference)
#include <cuda_runtime.h>
#include <cstdint>
#include <cstddef>

// ---------------------------------------------------------------------------
// BlocDiagLinear: out[b, n*128+r] = sum_c x[b, n*128+c] * blocks[n, r, c]
// 64 GEMMs (M=4096, N=128, K=128) fp32 -> mma.sync.m16n8k8.tf32, fp32 accum.
//
// R11: persistent CTAs. Grid = 296 (2/SM, single wave). Each CTA processes
// tiles t = bid + i*296 (tile: n = t>>5, m0 = (t&31)*128). The 3-stage
// cp.async ring runs continuously across tile boundaries: flat chunk stream
// (4 K-chunks of 32 per tile), buffers rotate mod 3, ring fill paid once.
// Tail handled with empty commit_group so wait_group 2 holds throughout.
// Fragment/mma math identical to R10 (HW tf32 truncation of raw fp32).
// ---------------------------------------------------------------------------

static constexpr int THREADS = 256;
static constexpr int NCTA    = 296;                  // 2 per SM x 148 SMs
static constexpr int NTILES  = 2048;                 // 64 n-blocks x 32 m-tiles
static constexpr int STAGE_BYTES = 32768;            // A 16KB + B 16KB
static constexpr int SMEM_BYTES  = 3 * STAGE_BYTES;  // 98304 -> 2 CTAs/SM

__device__ __forceinline__ uint32_t smem_u32(const void* p) {
    uint32_t a;
    asm("{ .reg .u64 t; cvta.to.shared.u64 t, %1; cvt.u32.u64 %0, t; }"
        : "=r"(a) : "l"(p));
    return a;
}

// Issue one K=32 chunk (A: x tile, B: blocks[n]) via cp.async.
__device__ __forceinline__ void issue_stage(uint32_t sbase,
                                            const float* __restrict__ xg,
                                            const float* __restrict__ bg,
                                            int s)
{
    #pragma unroll
    for (int it = 0; it < 4; it++) {
        const int j   = threadIdx.x + it * 256;   // 0..1023 int4 atoms
        const int row = j >> 3;                   // 0..127
        const int c   = j & 7;                    // 16B atom within 128B row
        const uint32_t sw = (uint32_t)((c ^ (row & 7)) << 4);
        const uint32_t dA = sbase + row * 128 + sw;
        const float* sA = xg + (size_t)row * 8192 + s * 32 + c * 4;
        asm volatile("cp.async.cg.shared.global [%0], [%1], 16;"
                     :: "r"(dA), "l"(sA));
        const uint32_t dB = sbase + 16384 + row * 128 + sw;
        const float* sB = bg + row * 128 + s * 32 + c * 4;
        asm volatile("cp.async.cg.shared.global [%0], [%1], 16;"
                     :: "r"(dB), "l"(sB));
    }
    asm volatile("cp.async.commit_group;" ::: "memory");
}

// Issue flat chunk qq (tile qq>>2, K-chunk qq&3), or an empty group past end.
__device__ __forceinline__ void issue_chunk(uint32_t sb, int qq, int Q, int bid,
                                            const float* __restrict__ x,
                                            const float* __restrict__ blocks)
{
    if (qq < Q) {
        const int t  = bid + (qq >> 2) * NCTA;
        const int n  = t >> 5;
        const int m0 = (t & 31) * 128;
        const float* xg = x + (size_t)m0 * 8192 + n * 128;
        const float* bg = blocks + (size_t)n * 16384;
        issue_stage(sb + (uint32_t)(qq % 3) * STAGE_BYTES, xg, bg, qq & 3);
    } else {
        asm volatile("cp.async.commit_group;" ::: "memory");
    }
}

// Compute one K=32 chunk (4 k-steps of m16n8k8). Raw fp32 fragments feed the
// tf32 mma directly; HW truncation handles the tf32 conversion.
__device__ __forceinline__ void compute_stage(uint32_t abase, uint32_t bbase,
                                              int mrow, int ncol, int lane,
                                              float acc[2][8][4])
{
    const int t4 = lane >> 3;     // tile index within ldmatrix.x4
    const int tr = lane & 7;      // row within tile

    #pragma unroll
    for (int kk = 0; kk < 4; kk++) {
        uint32_t a[2][4];
        #pragma unroll
        for (int i = 0; i < 2; i++) {
            const int r = mrow + 16 * i + ((t4 & 1) << 3) + tr;
            const int c = 2 * kk + (t4 >> 1);
            const uint32_t addr = abase + r * 128 + ((uint32_t)(c ^ (r & 7)) << 4);
            asm volatile(
                "ldmatrix.sync.aligned.m8n8.x4.shared.b16 {%0,%1,%2,%3}, [%4];"
                : "=r"(a[i][0]), "=r"(a[i][1]), "=r"(a[i][2]), "=r"(a[i][3])
                : "r"(addr));
        }

        uint32_t b[8][2];
        #pragma unroll
        for (int p = 0; p < 4; p++) {
            const int rn = ncol + (2 * p + (t4 >> 1)) * 8 + tr;
            const int c  = 2 * kk + (t4 & 1);
            const uint32_t addr = bbase + rn * 128 + ((uint32_t)(c ^ (rn & 7)) << 4);
            asm volatile(
                "ldmatrix.sync.aligned.m8n8.x4.shared.b16 {%0,%1,%2,%3}, [%4];"
                : "=r"(b[2 * p][0]), "=r"(b[2 * p][1]),
                  "=r"(b[2 * p + 1][0]), "=r"(b[2 * p + 1][1])
                : "r"(addr));
        }

        #pragma unroll
        for (int jj = 0; jj < 8; jj++)
            #pragma unroll
            for (int i = 0; i < 2; i++) {
                asm volatile(
                    "mma.sync.aligned.m16n8k8.row.col.f32.tf32.tf32.f32 "
                    "{%0,%1,%2,%3}, {%4,%5,%6,%7}, {%8,%9}, {%0,%1,%2,%3};"
                    : "+f"(acc[i][jj][0]), "+f"(acc[i][jj][1]),
                      "+f"(acc[i][jj][2]), "+f"(acc[i][jj][3])
                    : "r"(a[i][0]), "r"(a[i][1]), "r"(a[i][2]), "r"(a[i][3]),
                      "r"(b[jj][0]), "r"(b[jj][1]));
            }
    }
}

__global__ void __launch_bounds__(THREADS, 2)
bdl_mma_kernel(const float* __restrict__ x,
               const float* __restrict__ blocks,
               float* __restrict__ out)
{
    extern __shared__ char smem[];
    const uint32_t sb = smem_u32(smem);

    const int tid  = threadIdx.x;
    const int wid  = tid >> 5;
    const int lane = tid & 31;
    const int g    = lane >> 2;
    const int tig  = lane & 3;
    const int bid  = blockIdx.x;

    const int mrow = (wid >> 1) * 32;
    const int ncol = (wid & 1) * 64;

    // number of tiles for this CTA; flat chunk count
    const int cnt = (NTILES - bid + NCTA - 1) / NCTA;
    const int Q   = cnt * 4;

    float acc[2][8][4];
    #pragma unroll
    for (int i = 0; i < 2; i++)
        #pragma unroll
        for (int j = 0; j < 8; j++)
            #pragma unroll
            for (int v = 0; v < 4; v++)
                acc[i][j][v] = 0.0f;

    // ---- prologue: fill ring ----
    issue_chunk(sb, 0, Q, bid, x, blocks);
    issue_chunk(sb, 1, Q, bid, x, blocks);
    issue_chunk(sb, 2, Q, bid, x, blocks);

    // ---- flat chunk stream ----
    for (int q = 0; q < Q; q++) {
        asm volatile("cp.async.wait_group 2;" ::: "memory");
        __syncthreads();
        const uint32_t buf = sb + (uint32_t)(q % 3) * STAGE_BYTES;
        compute_stage(buf, buf + 16384, mrow, ncol, lane, acc);
        __syncthreads();
        issue_chunk(sb, q + 3, Q, bid, x, blocks);   // refill the buffer just freed

        if ((q & 3) == 3) {
            // ---- tile complete: epilogue (overlaps in-flight cp.async) ----
            const int t  = bid + (q >> 2) * NCTA;
            const int n  = t >> 5;
            const int m0 = (t & 31) * 128;
            float* obase = out + (size_t)m0 * 8192 + n * 128;
            #pragma unroll
            for (int i = 0; i < 2; i++) {
                const int r0 = mrow + 16 * i + g;
                #pragma unroll
                for (int jj = 0; jj < 8; jj++) {
                    const int c = ncol + 8 * jj + 2 * tig;
                    *reinterpret_cast<float2*>(obase + (size_t)r0 * 8192 + c) =
                        make_float2(acc[i][jj][0], acc[i][jj][1]);
                    *reinterpret_cast<float2*>(obase + (size_t)(r0 + 8) * 8192 + c) =
                        make_float2(acc[i][jj][2], acc[i][jj][3]);
                    acc[i][jj][0] = 0.0f; acc[i][jj][1] = 0.0f;
                    acc[i][jj][2] = 0.0f; acc[i][jj][3] = 0.0f;
                }
            }
        }
    }
}

extern "C" void kernel_launch(void* const* d_in, const int* in_sizes, int n_in,
                              void* d_out, int out_size)
{
    (void)in_sizes; (void)n_in; (void)out_size;
    const float* x      = (const float*)d_in[0];   // [4096, 8192]
    const float* blocks = (const float*)d_in[1];   // [64, 128, 128]
    float* out          = (float*)d_out;           // [4096, 8192]

    cudaFuncSetAttribute(bdl_mma_kernel,
                         cudaFuncAttributeMaxDynamicSharedMemorySize, SMEM_BYTES);
    bdl_mma_kernel<<<NCTA, THREADS, SMEM_BYTES>>>(x, blocks, out);
}